// round 11
// baseline (speedup 1.0000x reference)
#include <cuda_runtime.h>
#include <cuda_bf16.h>
#include <cstdint>

// Problem constants
#define BATCH   32
#define NSET    16384
#define DIM     128
#define CHUNKS  128
#define TILE_M  128
#define LDE     136          // C-staging leading dim (floats)

// ---------------------------------------------------------------------------
// Device scratch (static; no runtime allocation)
// ---------------------------------------------------------------------------
// x in MMA-A fragment order: per tile T (=b*128+nt), per block (mblk 0..7, k 0..7):
// 512B block at ((T*64 + mblk*8 + k)*32 + lane)*16; lane's uint4 = {a0,a1,a2,a3}:
//   a0 = x[r][k0],x[r][k0+1]; a1 = x[r+8][k0..]; a2 = x[r][k0+8..]; a3 = x[r+8][k0+8..]
//   with r = mblk*16 + lane/4, k0 = k*16 + (lane%4)*2   (bf16x2, low = even-k elem)
__device__ uint4 g_xfrag[(size_t)BATCH * 128 * 64 * 32];   // 128 MB
// w1 in MMA-B fragment order: block (npair 0..7, k 0..7):
//   lane uint4 = {b0(n0),b1(n0),b0(n0+8),b1(n0+8)},
//   b0 = w1[k0][n],w1[k0+1][n]; b1 = k0+8; n0 = npair*16 + lane/4
__device__ uint4 g_w1frag[2048];                           // 32 KB
__device__ float g_partial[BATCH * CHUNKS * DIM];          // 2 MB
__device__ float g_pooled[BATCH * DIM];                    // 16 KB

// ---------------------------------------------------------------------------
// Helpers
// ---------------------------------------------------------------------------
#define DI __device__ __forceinline__

#define MMA16816(c, a, b0, b1)                                                \
    asm volatile("mma.sync.aligned.m16n8k16.row.col.f32.bf16.bf16.f32 "       \
                 "{%0,%1,%2,%3}, {%4,%5,%6,%7}, {%8,%9}, {%0,%1,%2,%3};"      \
                 : "+f"((c)[0]), "+f"((c)[1]), "+f"((c)[2]), "+f"((c)[3])     \
                 : "r"((a)[0]), "r"((a)[1]), "r"((a)[2]), "r"((a)[3]),        \
                   "r"(b0), "r"(b1))

DI uint32_t bf16x2(float lo, float hi) {
    uint32_t r;
    asm("cvt.rn.bf16x2.f32 %0, %1, %2;" : "=r"(r) : "f"(hi), "f"(lo));
    return r;
}

// ---------------------------------------------------------------------------
// Pass 1: column sums + bf16 conversion of x into FRAGMENT-ORDER global image.
// grid (CHUNKS, BATCH), 256 thr.  One 128x128 tile per CTA.
// ---------------------------------------------------------------------------
__global__ void __launch_bounds__(256)
sum_cvt_kernel(const float* __restrict__ x) {
    __shared__ uint32_t tile[128 * 68];        // bf16 tile, stride 136 elems (68 words)
    __shared__ float4 red[8][32];

    const int b = blockIdx.y, nt = blockIdx.x;
    const int tid = threadIdx.x, w8 = tid >> 5, lane = tid & 31;
    const size_t base = (size_t)(b * NSET + nt * TILE_M) * 32;   // float4 units
    const float4* xt = reinterpret_cast<const float4*>(x) + base;
    uint2* t2 = reinterpret_cast<uint2*>(tile);

    float4 acc = make_float4(0.f, 0.f, 0.f, 0.f);
#pragma unroll
    for (int i = 0; i < 16; i++) {
        const int idx = i * 256 + tid;
        float4 v = __ldg(&xt[idx]);
        acc.x += v.x; acc.y += v.y; acc.z += v.z; acc.w += v.w;
        const int row = idx >> 5, col4 = idx & 31;
        t2[row * 34 + col4] = make_uint2(bf16x2(v.x, v.y), bf16x2(v.z, v.w));
    }
    red[w8][lane] = acc;
    __syncthreads();

    // warp 0: finish the deterministic column-sum reduction
    if (w8 == 0) {
        float4 t = red[0][lane];
#pragma unroll
        for (int j = 1; j < 8; j++) {
            float4 a = red[j][lane];
            t.x += a.x; t.y += a.y; t.z += a.z; t.w += a.w;
        }
        reinterpret_cast<float4*>(
            &g_partial[(size_t)(b * CHUNKS + nt) * DIM])[lane] = t;
    }

    // all warps: emit fragment-order blocks (8 blocks per warp), coalesced STG.128
    const uint32_t T = (uint32_t)(b * 128 + nt);
    const uint32_t r  = (uint32_t)(lane >> 2);      // within 16-row block
    const uint32_t kw = (uint32_t)(lane & 3);
#pragma unroll
    for (int bi = 0; bi < 8; bi++) {
        const int blk = bi * 8 + w8;                // mblk = blk>>3, kstep = blk&7
        const uint32_t mblk = (uint32_t)blk >> 3, kstep = (uint32_t)blk & 7u;
        const uint32_t w0 = (mblk * 16 + r) * 68 + kstep * 8 + kw;
        uint4 v;
        v.x = tile[w0];
        v.y = tile[w0 + 8 * 68];
        v.z = tile[w0 + 4];
        v.w = tile[w0 + 8 * 68 + 4];
        g_xfrag[((size_t)T * 64 + blk) * 32 + lane] = v;
    }
}

// ---------------------------------------------------------------------------
// Pass 2: blocks 0..31 -> pooled[b]; block 32 -> w1 fragment image.
// ---------------------------------------------------------------------------
__global__ void __launch_bounds__(128)
prep_kernel(const float* __restrict__ w1, const float* __restrict__ w2,
            const float* __restrict__ bias) {
    const int t = threadIdx.x;
    if (blockIdx.x == 32) {
        const int lane = t & 31;
        const int n0 = lane >> 2;                   // within 16-n pair-block
        const int k0 = (lane & 3) * 2;
#pragma unroll 4
        for (int blk = t >> 5; blk < 64; blk += 4) {
            const int npair = blk >> 3, kstep = blk & 7;
            const int n = npair * 16 + n0;
            const int k = kstep * 16 + k0;
            uint4 v;
            v.x = bf16x2(w1[k * DIM + n],           w1[(k + 1) * DIM + n]);
            v.y = bf16x2(w1[(k + 8) * DIM + n],     w1[(k + 9) * DIM + n]);
            v.z = bf16x2(w1[k * DIM + n + 8],       w1[(k + 1) * DIM + n + 8]);
            v.w = bf16x2(w1[(k + 8) * DIM + n + 8], w1[(k + 9) * DIM + n + 8]);
            g_w1frag[blk * 32 + lane] = v;
        }
        return;
    }
    const int b = blockIdx.x;
    __shared__ float xs[DIM];
    float s = 0.f;
#pragma unroll 8
    for (int c = 0; c < CHUNKS; c++)
        s += g_partial[(size_t)(b * CHUNKS + c) * DIM + t];
    xs[t] = s;
    __syncthreads();
    float p = bias[t];
#pragma unroll 8
    for (int d = 0; d < DIM; d++)
        p += xs[d] * w2[d * DIM + t];
    g_pooled[b * DIM + t] = p;
}

// ---------------------------------------------------------------------------
// Pass 3: out = x @ w1 + pooled.  Operands loaded DIRECTLY from fragment-order
// global images (no ldmatrix, no A/B SMEM, one __syncthreads total).
// grid (NSET/TILE_M, BATCH), 256 thr (8 warps = 2m x 4n, warp tile 64x32).
// SMEM: C staging 128 x LDE floats (69632) + pooled row (512).
// ---------------------------------------------------------------------------
#define SMEM_BYTES (69632 + 512)

__global__ void __launch_bounds__(256, 2)
ell_main(float* __restrict__ out) {
    extern __shared__ char smem[];
    float* Cs = reinterpret_cast<float*>(smem);
    float* ps = reinterpret_cast<float*>(smem + 69632);

    const int tid = threadIdx.x, lane = tid & 31, wid = tid >> 5;
    const int wm = wid >> 2, wn = wid & 3;
    const int b = blockIdx.y, nt = blockIdx.x;
    const uint32_t T = (uint32_t)(b * 128 + nt);

    const uint4* Ab = g_xfrag + (size_t)T * 2048 + lane;   // + (mblk*8+k)*32
    const uint4* Bb = g_w1frag + lane;                      // + (npair*8+k)*32

    float c[4][4][4];
#pragma unroll
    for (int mf = 0; mf < 4; mf++)
#pragma unroll
        for (int nf = 0; nf < 4; nf++)
#pragma unroll
            for (int e = 0; e < 4; e++) c[mf][nf][e] = 0.f;

    if (tid < DIM) ps[tid] = g_pooled[b * DIM + tid];

    // A double-buffered (DRAM first-touch); B is L1-resident (32 KB, hot).
    uint4 abuf[2][4];
#pragma unroll
    for (int mf = 0; mf < 4; mf++)
        abuf[0][mf] = __ldg(Ab + ((wm * 4 + mf) * 8 + 0) * 32);

#pragma unroll
    for (int k = 0; k < 8; k++) {
        const int cur = k & 1;
        if (k < 7) {
#pragma unroll
            for (int mf = 0; mf < 4; mf++)
                abuf[cur ^ 1][mf] = __ldg(Ab + ((wm * 4 + mf) * 8 + k + 1) * 32);
        }
        uint4 bb[2];
#pragma unroll
        for (int pp = 0; pp < 2; pp++)
            bb[pp] = __ldg(Bb + ((wn * 2 + pp) * 8 + k) * 32);
#pragma unroll
        for (int mf = 0; mf < 4; mf++) {
            const uint32_t* a = reinterpret_cast<const uint32_t*>(&abuf[cur][mf]);
#pragma unroll
            for (int nf = 0; nf < 4; nf++) {
                const int p = nf >> 1;
                const uint32_t b0 = (nf & 1) ? bb[p].z : bb[p].x;
                const uint32_t b1 = (nf & 1) ? bb[p].w : bb[p].y;
                MMA16816(c[mf][nf], a, b0, b1);
            }
        }
    }

    // --- C staging to SMEM (stride LDE) ---
#pragma unroll
    for (int mf = 0; mf < 4; mf++) {
        const int row0 = wm * 64 + mf * 16 + (lane >> 2);
#pragma unroll
        for (int nf = 0; nf < 4; nf++) {
            const int col = wn * 32 + nf * 8 + (lane & 3) * 2;
            *reinterpret_cast<float2*>(&Cs[row0 * LDE + col]) =
                make_float2(c[mf][nf][0], c[mf][nf][1]);
            *reinterpret_cast<float2*>(&Cs[(row0 + 8) * LDE + col]) =
                make_float2(c[mf][nf][2], c[mf][nf][3]);
        }
    }
    __syncthreads();

    // --- Coalesced epilogue: row-linear float4 + pooled add + STG.128 ---
    float4* ob = reinterpret_cast<float4*>(out + (size_t)(b * NSET + nt * TILE_M) * DIM);
    const int col4 = tid & 31;
    const float4 pv = reinterpret_cast<const float4*>(ps)[col4];
#pragma unroll
    for (int i = 0; i < 16; i++) {
        const int idx = i * 256 + tid;
        const int row = idx >> 5;
        float4 v = *reinterpret_cast<float4*>(&Cs[row * LDE + col4 * 4]);
        v.x += pv.x; v.y += pv.y; v.z += pv.z; v.w += pv.w;
        ob[idx] = v;
    }
}

// ---------------------------------------------------------------------------
// Launch
// ---------------------------------------------------------------------------
extern "C" void kernel_launch(void* const* d_in, const int* in_sizes, int n_in,
                              void* d_out, int out_size) {
    const float* x    = (const float*)d_in[0];
    const float* w1   = (const float*)d_in[1];
    const float* w2   = (const float*)d_in[2];
    const float* bias = (const float*)d_in[3];
    float* out = (float*)d_out;

    static bool attr_done = false;
    if (!attr_done) {
        cudaFuncSetAttribute(ell_main, cudaFuncAttributeMaxDynamicSharedMemorySize,
                             SMEM_BYTES);
        attr_done = true;
    }

    sum_cvt_kernel<<<dim3(CHUNKS, BATCH), 256>>>(x);
    prep_kernel<<<33, 128>>>(w1, w2, bias);
    ell_main<<<dim3(NSET / TILE_M, BATCH), 256, SMEM_BYTES>>>(out);
}

// round 15
// speedup vs baseline: 1.2794x; 1.2794x over previous
#include <cuda_runtime.h>
#include <cuda_bf16.h>
#include <cstdint>

// Problem constants
#define BATCH   32
#define NSET    16384
#define DIM     128
#define CHUNKS  128
#define TILE_M  128

#define LDE     136          // padded leading dim (elements)
#define LDBYTES 272          // bf16 row stride in bytes

// ---------------------------------------------------------------------------
// Device scratch (static; no runtime allocation)
// ---------------------------------------------------------------------------
__device__ float g_partial[BATCH * CHUNKS * DIM];        // 2 MB
__device__ float g_pooled[BATCH * DIM];                  // 16 KB
__device__ uint4 g_w1t[2176];                            // 34816 B: w1^T bf16 [n][k] ld=LDE
__device__ uint2 g_xbf[(size_t)BATCH * NSET * 32];       // 128 MB: x as bf16 [b][n][128]

// ---------------------------------------------------------------------------
// Helpers
// ---------------------------------------------------------------------------
#define DI __device__ __forceinline__

DI uint32_t smem_u32(const void* p) {
    uint32_t a;
    asm("{ .reg .u64 t; cvta.to.shared.u64 t, %1; cvt.u32.u64 %0, t; }"
        : "=r"(a) : "l"(p));
    return a;
}

#define LDSM_X4(r, addr)                                                      \
    asm volatile("ldmatrix.sync.aligned.m8n8.x4.shared.b16 {%0,%1,%2,%3}, [%4];" \
                 : "=r"((r)[0]), "=r"((r)[1]), "=r"((r)[2]), "=r"((r)[3])     \
                 : "r"(addr))

#define MMA16816(c, a, b0, b1)                                                \
    asm volatile("mma.sync.aligned.m16n8k16.row.col.f32.bf16.bf16.f32 "       \
                 "{%0,%1,%2,%3}, {%4,%5,%6,%7}, {%8,%9}, {%0,%1,%2,%3};"      \
                 : "+f"((c)[0]), "+f"((c)[1]), "+f"((c)[2]), "+f"((c)[3])     \
                 : "r"((a)[0]), "r"((a)[1]), "r"((a)[2]), "r"((a)[3]),        \
                   "r"(b0), "r"(b1))

// ---------------------------------------------------------------------------
// Pass 1: partial column-sums + bf16 conversion of x (linear image).
// grid (CHUNKS, BATCH), 256 thr.  One 128x128 tile per CTA.  [verified 57us]
// ---------------------------------------------------------------------------
__global__ void __launch_bounds__(256)
sum_cvt_kernel(const float* __restrict__ x) {
    const int b = blockIdx.y, chunk = blockIdx.x;
    const int tid = threadIdx.x, w8 = tid >> 5, l = tid & 31;
    const size_t base = (size_t)(b * NSET + chunk * TILE_M) * 32;   // float4 units
    const float4* xt = reinterpret_cast<const float4*>(x) + base;
    uint2* xb = g_xbf + base;

    float4 acc = make_float4(0.f, 0.f, 0.f, 0.f);
#pragma unroll
    for (int i = 0; i < 16; i++) {
        const int idx = i * 256 + tid;
        float4 v = __ldg(&xt[idx]);
        acc.x += v.x; acc.y += v.y; acc.z += v.z; acc.w += v.w;
        uint32_t h01, h23;
        asm("cvt.rn.bf16x2.f32 %0, %1, %2;" : "=r"(h01) : "f"(v.y), "f"(v.x));
        asm("cvt.rn.bf16x2.f32 %0, %1, %2;" : "=r"(h23) : "f"(v.w), "f"(v.z));
        xb[idx] = make_uint2(h01, h23);
    }

    __shared__ float4 red[8][32];
    red[w8][l] = acc;
    __syncthreads();
    if (w8 == 0) {
        float4 t = red[0][l];
#pragma unroll
        for (int j = 1; j < 8; j++) {
            float4 a = red[j][l];
            t.x += a.x; t.y += a.y; t.z += a.z; t.w += a.w;
        }
        reinterpret_cast<float4*>(&g_partial[(size_t)(b * CHUNKS + chunk) * DIM])[l] = t;
    }
}

// ---------------------------------------------------------------------------
// Pass 2: blocks 0..31 -> pooled[b] (fp32 exact); block 32 -> w1^T bf16 image.
// ---------------------------------------------------------------------------
__global__ void __launch_bounds__(128)
prep_kernel(const float* __restrict__ w1, const float* __restrict__ w2,
            const float* __restrict__ bias) {
    const int t = threadIdx.x;
    if (blockIdx.x == 32) {
        __nv_bfloat16* dst = reinterpret_cast<__nv_bfloat16*>(g_w1t);
#pragma unroll 4
        for (int k = 0; k < DIM; k++)
            dst[t * LDE + k] = __float2bfloat16(w1[k * DIM + t]);  // n = t
        return;
    }
    const int b = blockIdx.x;
    __shared__ float xs[DIM];
    float s = 0.f;
#pragma unroll 8
    for (int c = 0; c < CHUNKS; c++)
        s += g_partial[(size_t)(b * CHUNKS + c) * DIM + t];
    xs[t] = s;
    __syncthreads();
    float p = bias[t];
#pragma unroll 8
    for (int d = 0; d < DIM; d++)
        p += xs[d] * w2[d * DIM + t];
    g_pooled[b * DIM + t] = p;
}

// ---------------------------------------------------------------------------
// Pass 3: out = x @ w1 (mma.sync bf16) + pooled.
// grid (NSET/TILE_M, BATCH), 256 thr (8 warps = 2m x 4n, warp tile 64x32).
// A from bf16 image (uint4 LDG, batched), B = w1^T smem image, ldmatrix feed,
// C staged through SMEM for coalesced STG.128.   [R8 structure, bf16 A]
// ---------------------------------------------------------------------------
#define AB_BYTES   69632
#define SMEM_BYTES (AB_BYTES + 512)

__global__ void __launch_bounds__(256, 2)
ell_main(float* __restrict__ out) {
    extern __shared__ char smem[];
    const uint32_t sb = smem_u32(smem);
    const uint32_t A0 = sb;
    const uint32_t B0 = sb + 34816u;
    float* Cs = reinterpret_cast<float*>(smem);             // staging (post-MMA)
    float* ps = reinterpret_cast<float*>(smem + AB_BYTES);  // pooled row

    const int tid = threadIdx.x, lane = tid & 31, wid = tid >> 5;
    const int b = blockIdx.y, nt = blockIdx.x;

    // --- B: linear copy of w1^T image (L2-resident, 34816 B) ---
    {
        uint4* Bs4 = reinterpret_cast<uint4*>(smem + 34816);
#pragma unroll
        for (int i = 0; i < 9; i++) {
            int idx = i * 256 + tid;
            if (idx < 2176) Bs4[idx] = g_w1t[idx];
        }
    }

    // --- A: 128x128 bf16 tile via uint4 loads (batched MLP), stride LDBYTES ---
    const uint4* xb = reinterpret_cast<const uint4*>(
        g_xbf + (size_t)(b * NSET + nt * TILE_M) * 32);
#pragma unroll
    for (int i = 0; i < 8; i++) {
        const int idx = i * 256 + tid;              // 0..2047 uint4
        uint4 v = __ldg(&xb[idx]);
        const uint32_t row = (uint32_t)idx >> 4, col8 = (uint32_t)idx & 15u;
        asm volatile("st.shared.v4.b32 [%0], {%1,%2,%3,%4};"
                     :: "r"(A0 + row * LDBYTES + col8 * 16u),
                        "r"(v.x), "r"(v.y), "r"(v.z), "r"(v.w));
    }

    if (tid < DIM) ps[tid] = g_pooled[b * DIM + tid];
    __syncthreads();

    // --- MMA mainloop: warp (wm, wn) owns 64 rows x 32 cols ---
    const int wm = wid >> 2;   // 0..1
    const int wn = wid & 3;    // 0..3

    float c[4][4][4];
#pragma unroll
    for (int mf = 0; mf < 4; mf++)
#pragma unroll
        for (int nf = 0; nf < 4; nf++)
#pragma unroll
            for (int e = 0; e < 4; e++) c[mf][nf][e] = 0.f;

    const uint32_t lrow  = (uint32_t)(lane & 15);
    const uint32_t khalf = (uint32_t)(lane >> 4) * 16u;  // 8 elems * 2B
    uint32_t aBase[4], bBase[2];
#pragma unroll
    for (int mf = 0; mf < 4; mf++)
        aBase[mf] = A0 + (wm * 64 + mf * 16 + lrow) * LDBYTES + khalf;
#pragma unroll
    for (int p = 0; p < 2; p++)
        bBase[p] = B0 + (wn * 32 + p * 16 + lrow) * LDBYTES + khalf;

#pragma unroll
    for (int k = 0; k < 8; k++) {
        const uint32_t koff = (uint32_t)k * 32u;
        uint32_t a[4][4], bb[2][4];
#pragma unroll
        for (int mf = 0; mf < 4; mf++) LDSM_X4(a[mf], aBase[mf] + koff);
#pragma unroll
        for (int p = 0; p < 2; p++)   LDSM_X4(bb[p], bBase[p] + koff);
#pragma unroll
        for (int mf = 0; mf < 4; mf++) {
#pragma unroll
            for (int nf = 0; nf < 4; nf++) {
                const int p = nf >> 1, o = nf & 1;
                MMA16816(c[mf][nf], a[mf], bb[p][o], bb[p][o + 2]);
            }
        }
    }

    __syncthreads();   // all warps done reading A/B before C staging overwrites

    // --- C staging to SMEM (stride LDE floats; conflict-free) ---
#pragma unroll
    for (int mf = 0; mf < 4; mf++) {
        const int row0 = wm * 64 + mf * 16 + (lane >> 2);
#pragma unroll
        for (int nf = 0; nf < 4; nf++) {
            const int col = wn * 32 + nf * 8 + (lane & 3) * 2;
            *reinterpret_cast<float2*>(&Cs[row0 * LDE + col]) =
                make_float2(c[mf][nf][0], c[mf][nf][1]);
            *reinterpret_cast<float2*>(&Cs[(row0 + 8) * LDE + col]) =
                make_float2(c[mf][nf][2], c[mf][nf][3]);
        }
    }
    __syncthreads();

    // --- Coalesced epilogue: row-linear float4 read + pooled add + STG.128 ---
    float4* ob = reinterpret_cast<float4*>(out + (size_t)(b * NSET + nt * TILE_M) * DIM);
    const int col4 = tid & 31;
    const float4 pv = reinterpret_cast<const float4*>(ps)[col4];
#pragma unroll
    for (int i = 0; i < 16; i++) {
        const int idx = i * 256 + tid;
        const int row = idx >> 5;
        float4 v = *reinterpret_cast<float4*>(&Cs[row * LDE + col4 * 4]);
        v.x += pv.x; v.y += pv.y; v.z += pv.z; v.w += pv.w;
        ob[idx] = v;
    }
}

// ---------------------------------------------------------------------------
// Launch
// ---------------------------------------------------------------------------
extern "C" void kernel_launch(void* const* d_in, const int* in_sizes, int n_in,
                              void* d_out, int out_size) {
    const float* x    = (const float*)d_in[0];
    const float* w1   = (const float*)d_in[1];
    const float* w2   = (const float*)d_in[2];
    const float* bias = (const float*)d_in[3];
    float* out = (float*)d_out;

    static bool attr_done = false;
    if (!attr_done) {
        cudaFuncSetAttribute(ell_main, cudaFuncAttributeMaxDynamicSharedMemorySize,
                             SMEM_BYTES);
        attr_done = true;
    }

    sum_cvt_kernel<<<dim3(CHUNKS, BATCH), 256>>>(x);
    prep_kernel<<<33, 128>>>(w1, w2, bias);
    ell_main<<<dim3(NSET / TILE_M, BATCH), 256, SMEM_BYTES>>>(out);
}

// round 16
// speedup vs baseline: 1.3992x; 1.0936x over previous
#include <cuda_runtime.h>
#include <cuda_bf16.h>
#include <cstdint>

// Problem constants
#define BATCH   32
#define NSET    16384
#define DIM     128
#define CHUNKS  128
#define TILE_M  128

#define LDBYTES 272          // bf16 A-tile row stride in bytes (136 elems)

// ---------------------------------------------------------------------------
// Device scratch (static; no runtime allocation)
// ---------------------------------------------------------------------------
__device__ float g_partial[BATCH * CHUNKS * DIM];        // 2 MB
__device__ float g_pooled[BATCH * DIM];                  // 16 KB
__device__ uint2 g_xbf[(size_t)BATCH * NSET * 32];       // 128 MB: x as bf16 linear
// w1 in MMA-B fragment order (verified R10): block (npair 0..7, kstep 0..7):
//   lane uint4 = {b0(n0), b1(n0), b0(n0+8), b1(n0+8)}, n0 = npair*16 + lane/4,
//   b0 = w1[k0][n],w1[k0+1][n]; b1 = same at k0+8; k0 = kstep*16 + (lane%4)*2
__device__ uint4 g_w1frag[2048];                         // 32 KB

// ---------------------------------------------------------------------------
// Helpers
// ---------------------------------------------------------------------------
#define DI __device__ __forceinline__

DI uint32_t smem_u32(const void* p) {
    uint32_t a;
    asm("{ .reg .u64 t; cvta.to.shared.u64 t, %1; cvt.u32.u64 %0, t; }"
        : "=r"(a) : "l"(p));
    return a;
}

DI uint32_t bf16x2(float lo, float hi) {
    uint32_t r;
    asm("cvt.rn.bf16x2.f32 %0, %1, %2;" : "=r"(r) : "f"(hi), "f"(lo));
    return r;
}

#define LDSM_X4(r, addr)                                                      \
    asm volatile("ldmatrix.sync.aligned.m8n8.x4.shared.b16 {%0,%1,%2,%3}, [%4];" \
                 : "=r"((r)[0]), "=r"((r)[1]), "=r"((r)[2]), "=r"((r)[3])     \
                 : "r"(addr))

#define MMA16816(c, a, b0, b1)                                                \
    asm volatile("mma.sync.aligned.m16n8k16.row.col.f32.bf16.bf16.f32 "       \
                 "{%0,%1,%2,%3}, {%4,%5,%6,%7}, {%8,%9}, {%0,%1,%2,%3};"      \
                 : "+f"((c)[0]), "+f"((c)[1]), "+f"((c)[2]), "+f"((c)[3])     \
                 : "r"((a)[0]), "r"((a)[1]), "r"((a)[2]), "r"((a)[3]),        \
                   "r"(b0), "r"(b1))

// ---------------------------------------------------------------------------
// Pass 1: partial column-sums + bf16 conversion of x.  [verified 55us, 82% DRAM]
// ---------------------------------------------------------------------------
__global__ void __launch_bounds__(256)
sum_cvt_kernel(const float* __restrict__ x) {
    const int b = blockIdx.y, chunk = blockIdx.x;
    const int tid = threadIdx.x, w8 = tid >> 5, l = tid & 31;
    const size_t base = (size_t)(b * NSET + chunk * TILE_M) * 32;
    const float4* xt = reinterpret_cast<const float4*>(x) + base;
    uint2* xb = g_xbf + base;

    float4 acc = make_float4(0.f, 0.f, 0.f, 0.f);
#pragma unroll
    for (int i = 0; i < 16; i++) {
        const int idx = i * 256 + tid;
        float4 v = __ldg(&xt[idx]);
        acc.x += v.x; acc.y += v.y; acc.z += v.z; acc.w += v.w;
        xb[idx] = make_uint2(bf16x2(v.x, v.y), bf16x2(v.z, v.w));
    }

    __shared__ float4 red[8][32];
    red[w8][l] = acc;
    __syncthreads();
    if (w8 == 0) {
        float4 t = red[0][l];
#pragma unroll
        for (int j = 1; j < 8; j++) {
            float4 a = red[j][l];
            t.x += a.x; t.y += a.y; t.z += a.z; t.w += a.w;
        }
        reinterpret_cast<float4*>(&g_partial[(size_t)(b * CHUNKS + chunk) * DIM])[l] = t;
    }
}

// ---------------------------------------------------------------------------
// Pass 2: blocks 0..31 -> pooled[b] (exact fp32); block 32 -> w1 frag image.
// ---------------------------------------------------------------------------
__global__ void __launch_bounds__(128)
prep_kernel(const float* __restrict__ w1, const float* __restrict__ w2,
            const float* __restrict__ bias) {
    const int t = threadIdx.x;
    if (blockIdx.x == 32) {
        const int lane = t & 31;
        const int n0 = lane >> 2;
        const int k0 = (lane & 3) * 2;
#pragma unroll 4
        for (int blk = t >> 5; blk < 64; blk += 4) {
            const int npair = blk >> 3, kstep = blk & 7;
            const int n = npair * 16 + n0;
            const int k = kstep * 16 + k0;
            uint4 v;
            v.x = bf16x2(w1[k * DIM + n],           w1[(k + 1) * DIM + n]);
            v.y = bf16x2(w1[(k + 8) * DIM + n],     w1[(k + 9) * DIM + n]);
            v.z = bf16x2(w1[k * DIM + n + 8],       w1[(k + 1) * DIM + n + 8]);
            v.w = bf16x2(w1[(k + 8) * DIM + n + 8], w1[(k + 9) * DIM + n + 8]);
            g_w1frag[blk * 32 + lane] = v;
        }
        return;
    }
    const int b = blockIdx.x;
    __shared__ float xs[DIM];
    float s = 0.f;
#pragma unroll 8
    for (int c = 0; c < CHUNKS; c++)
        s += g_partial[(size_t)(b * CHUNKS + c) * DIM + t];
    xs[t] = s;
    __syncthreads();
    float p = bias[t];
#pragma unroll 8
    for (int d = 0; d < DIM; d++)
        p += xs[d] * w2[d * DIM + t];
    g_pooled[b * DIM + t] = p;
}

// ---------------------------------------------------------------------------
// Pass 3: out = x @ w1 + pooled.
// 256 thr (8 warps = 2m x 4n, warp tile 64x32).  ONE __syncthreads total.
//   A: bf16 image -> SMEM (batched uint4 LDG) -> ldmatrix        [R15 path]
//   B: direct uint4 LDG from L1-resident fragment image          [R10 path]
//   C: stored straight from MMA fragments (full 32B sectors), pooled
//      pre-loaded into registers. No staging, no post-MMA syncs.
// ---------------------------------------------------------------------------
#define SMEM_BYTES 34816

__global__ void __launch_bounds__(256, 2)
ell_main(float* __restrict__ out) {
    extern __shared__ char smem[];
    const uint32_t A0 = smem_u32(smem);

    const int tid = threadIdx.x, lane = tid & 31, wid = tid >> 5;
    const int wm = wid >> 2;   // 0..1
    const int wn = wid & 3;    // 0..3
    const int b = blockIdx.y, nt = blockIdx.x;

    // --- A: 128x128 bf16 tile via batched uint4 LDG, stride LDBYTES ---
    const uint4* xb = reinterpret_cast<const uint4*>(
        g_xbf + (size_t)(b * NSET + nt * TILE_M) * 32);
#pragma unroll
    for (int i = 0; i < 8; i++) {
        const int idx = i * 256 + tid;              // 0..2047 uint4
        uint4 v = __ldg(&xb[idx]);
        const uint32_t row = (uint32_t)idx >> 4, col8 = (uint32_t)idx & 15u;
        asm volatile("st.shared.v4.b32 [%0], {%1,%2,%3,%4};"
                     :: "r"(A0 + row * LDBYTES + col8 * 16u),
                        "r"(v.x), "r"(v.y), "r"(v.z), "r"(v.w));
    }

    // --- pooled values for this lane's output columns (4 nf x 2 cols) ---
    float2 pv[4];
    {
        const float* pbase = g_pooled + b * DIM + wn * 32 + (lane & 3) * 2;
#pragma unroll
        for (int nf = 0; nf < 4; nf++)
            pv[nf] = __ldg(reinterpret_cast<const float2*>(pbase + nf * 8));
    }

    __syncthreads();

    // --- MMA mainloop ---
    float c[4][4][4];
#pragma unroll
    for (int mf = 0; mf < 4; mf++)
#pragma unroll
        for (int nf = 0; nf < 4; nf++)
#pragma unroll
            for (int e = 0; e < 4; e++) c[mf][nf][e] = 0.f;

    const uint32_t lrow  = (uint32_t)(lane & 15);
    const uint32_t khalf = (uint32_t)(lane >> 4) * 16u;
    uint32_t aBase[4];
#pragma unroll
    for (int mf = 0; mf < 4; mf++)
        aBase[mf] = A0 + (wm * 64 + mf * 16 + lrow) * LDBYTES + khalf;
    const uint4* Bb = g_w1frag + lane;              // + (npair*8 + k)*32

#pragma unroll
    for (int k = 0; k < 8; k++) {
        const uint32_t koff = (uint32_t)k * 32u;
        uint32_t a[4][4];
        uint4 bb[2];
#pragma unroll
        for (int mf = 0; mf < 4; mf++) LDSM_X4(a[mf], aBase[mf] + koff);
#pragma unroll
        for (int pp = 0; pp < 2; pp++)
            bb[pp] = __ldg(Bb + ((wn * 2 + pp) * 8 + k) * 32);
#pragma unroll
        for (int mf = 0; mf < 4; mf++) {
#pragma unroll
            for (int nf = 0; nf < 4; nf++) {
                const int p = nf >> 1;
                const uint32_t b0 = (nf & 1) ? bb[p].z : bb[p].x;
                const uint32_t b1 = (nf & 1) ? bb[p].w : bb[p].y;
                MMA16816(c[mf][nf], a[mf], b0, b1);
            }
        }
    }

    // --- Direct epilogue: frag pairs are contiguous 8B; warp packs 32B sectors ---
    float* obase = out + (size_t)(b * NSET + nt * TILE_M) * DIM;
#pragma unroll
    for (int mf = 0; mf < 4; mf++) {
        const int r0 = wm * 64 + mf * 16 + (lane >> 2);
#pragma unroll
        for (int nf = 0; nf < 4; nf++) {
            const int col = wn * 32 + nf * 8 + (lane & 3) * 2;
            *reinterpret_cast<float2*>(obase + (size_t)r0 * DIM + col) =
                make_float2(c[mf][nf][0] + pv[nf].x, c[mf][nf][1] + pv[nf].y);
            *reinterpret_cast<float2*>(obase + (size_t)(r0 + 8) * DIM + col) =
                make_float2(c[mf][nf][2] + pv[nf].x, c[mf][nf][3] + pv[nf].y);
        }
    }
}

// ---------------------------------------------------------------------------
// Launch
// ---------------------------------------------------------------------------
extern "C" void kernel_launch(void* const* d_in, const int* in_sizes, int n_in,
                              void* d_out, int out_size) {
    const float* x    = (const float*)d_in[0];
    const float* w1   = (const float*)d_in[1];
    const float* w2   = (const float*)d_in[2];
    const float* bias = (const float*)d_in[3];
    float* out = (float*)d_out;

    static bool attr_done = false;
    if (!attr_done) {
        cudaFuncSetAttribute(ell_main, cudaFuncAttributeMaxDynamicSharedMemorySize,
                             SMEM_BYTES);
        attr_done = true;
    }

    sum_cvt_kernel<<<dim3(CHUNKS, BATCH), 256>>>(x);
    prep_kernel<<<33, 128>>>(w1, w2, bias);
    ell_main<<<dim3(NSET / TILE_M, BATCH), 256, SMEM_BYTES>>>(out);
}